// round 1
// baseline (speedup 1.0000x reference)
#include <cuda_runtime.h>
#include <cuda_bf16.h>
#include <cstdint>

// Shapes are fixed by the problem: activation (16, 128, 114, 114) float32.
// Channels  0..31  : inactive (copy through)
// Channels 32..79  : 2x2 block-sign ReLU
// Channels 80..127 : 4x4 block-sign ReLU
//
// Sign chain (exact replication of the reference):
//   s    = int64( trunc(float32 block sum) )        (numpy astype truncates toward zero)
//   mean = s >> log2(nblk)                          (arithmetic shift == floor division)
//   q    = int16(mean >> 5)                         (wrap; cannot trigger at these magnitudes but kept exact)
//   sign = (q >= 0)
// out = in * (sign ? 1.0f : 0.0f)

#define H_DIM 114
#define W_DIM 114
#define IMG_ELEMS (H_DIM * W_DIM)   // 12996 floats, 51984 bytes (16B aligned per image)

__device__ __forceinline__ float sign_mul_2x2(float sum) {
    long long s = (long long)sum;     // trunc toward zero
    long long mean = s >> 2;          // floor div by 4
    short q = (short)(mean >> 5);
    return (q >= 0) ? 1.0f : 0.0f;
}

__device__ __forceinline__ float sign_mul_4x4(float sum) {
    long long s = (long long)sum;
    long long mean = s >> 4;          // floor div by 16
    short q = (short)(mean >> 5);
    return (q >= 0) ? 1.0f : 0.0f;
}

__global__ void __launch_bounds__(256)
block_relu_kernel(const float* __restrict__ in, float* __restrict__ out) {
    const int img = blockIdx.x;            // n*128 + c, 0..2047
    const int c = img & 127;
    const size_t base = (size_t)img * IMG_ELEMS;
    const float* __restrict__ src = in + base;
    float* __restrict__ dst = out + base;
    const int t = threadIdx.x;
    const int nt = blockDim.x;

    if (c < 32) {
        // ---- inactive: straight copy, float4 (image base is 16B aligned) ----
        const float4* __restrict__ s4 = (const float4*)src;
        float4* __restrict__ d4 = (float4*)dst;
        #pragma unroll 4
        for (int i = t; i < IMG_ELEMS / 4; i += nt) {   // 3249 float4s
            d4[i] = s4[i];
        }
    } else if (c < 80) {
        // ---- 2x2 blocks: 57 x 57 = 3249 blocks, no padding (114 even) ----
        for (int b = t; b < 57 * 57; b += nt) {
            const int bi = b / 57;
            const int bj = b - bi * 57;
            const int r0 = 2 * bi;
            const float2* __restrict__ p0 = (const float2*)(src + (size_t)r0 * W_DIM) + bj;
            const float2* __restrict__ p1 = (const float2*)(src + (size_t)(r0 + 1) * W_DIM) + bj;
            float2 a = *p0;
            float2 d = *p1;
            float sum = a.x + a.y + d.x + d.y;
            float m = sign_mul_2x2(sum);
            float2* __restrict__ q0 = (float2*)(dst + (size_t)r0 * W_DIM) + bj;
            float2* __restrict__ q1 = (float2*)(dst + (size_t)(r0 + 1) * W_DIM) + bj;
            *q0 = make_float2(a.x * m, a.y * m);
            *q1 = make_float2(d.x * m, d.y * m);
        }
    } else {
        // ---- 4x4 blocks: 29 x 29 = 841 blocks; last row/col partial (pad = 0) ----
        for (int b = t; b < 29 * 29; b += nt) {
            const int bi = b / 29;
            const int bj = b - bi * 29;
            const int r0 = 4 * bi;
            const int c0 = 4 * bj;
            const int nrows = (r0 + 4 <= H_DIM) ? 4 : (H_DIM - r0);   // 4 or 2
            const bool full = (c0 + 4 <= W_DIM);                      // last col block has 2 cols

            float2 v[4][2];
            float sum = 0.0f;
            #pragma unroll
            for (int r = 0; r < 4; r++) {
                if (r < nrows) {
                    const float2* __restrict__ p = (const float2*)(src + (size_t)(r0 + r) * W_DIM + c0);
                    v[r][0] = p[0];
                    sum += v[r][0].x + v[r][0].y;
                    if (full) {
                        v[r][1] = p[1];
                        sum += v[r][1].x + v[r][1].y;
                    }
                }
            }
            float m = sign_mul_4x4(sum);
            #pragma unroll
            for (int r = 0; r < 4; r++) {
                if (r < nrows) {
                    float2* __restrict__ q = (float2*)(dst + (size_t)(r0 + r) * W_DIM + c0);
                    q[0] = make_float2(v[r][0].x * m, v[r][0].y * m);
                    if (full) {
                        q[1] = make_float2(v[r][1].x * m, v[r][1].y * m);
                    }
                }
            }
        }
    }
}

extern "C" void kernel_launch(void* const* d_in, const int* in_sizes, int n_in,
                              void* d_out, int out_size) {
    (void)in_sizes; (void)n_in; (void)out_size;
    const float* act = (const float*)d_in[0];
    float* out = (float*)d_out;
    // 16 batches * 128 channels = 2048 images
    block_relu_kernel<<<2048, 256>>>(act, out);
}